// round 2
// baseline (speedup 1.0000x reference)
#include <cuda_runtime.h>
#include <math.h>

#define E   320
#define E3  960
#define KQ  128
#define TT  256
#define TM1 255
#define H   10
#define HD  32
#define SMAX 32768            // padded KV rows (max valid = 32640)
#define EPS 1e-5f

// ---------------- device scratch (static; no allocations) ----------------
__device__ float g_Wf[E * E3];          // fused weights, [e][o] (e-major), o in [0,960)
__device__ float g_bf[E3];              // fused bias
__device__ float g_owt[E * E];          // out_w transposed: [j][i]
__device__ float g_alpha[KQ * E];       // current alpha (K,E)
__device__ float g_q2[KQ * E];          // projected+scaled q (K,E)
__device__ float g_kT[H * HD * SMAX];   // K cache transposed: [h][d][s]
__device__ float g_v [H * SMAX * HD];   // V cache: [h][s][d]
__device__ float g_pm[2 * H * KQ];      // split partial max
__device__ float g_pl[2 * H * KQ];      // split partial sumexp
__device__ float g_po[2 * H * KQ * HD]; // split partial (unnormalized) out

// ---------------- one-time: fuse qkv_proj with MHA in_proj ----------------
// q2 = alpha @ (Wq@Wqkv_q)^T * scale + ... ; one block per output column o.
__global__ void fuse_weights(const float* __restrict__ qkvw, const float* __restrict__ qkvb,
                             const float* __restrict__ inw,  const float* __restrict__ inb)
{
    __shared__ float wrow[E];
    int o = blockIdx.x;            // 0..959
    int p = o / E;                 // 0=q,1=k,2=v
    int tid = threadIdx.x;         // 0..319
    wrow[tid] = inw[o * E + tid];
    __syncthreads();
    const float scale = 0.17677669529663687f;   // 1/sqrt(32)
    float acc = 0.f;
    int e = tid;
    #pragma unroll 4
    for (int j = 0; j < E; ++j)
        acc += wrow[j] * qkvw[(p * E + j) * E + e];
    if (p == 0) acc *= scale;
    g_Wf[e * E3 + o] = acc;
    if (tid < 32) {
        float s = 0.f;
        for (int j = tid; j < E; j += 32) s += wrow[j] * qkvb[p * E + j];
        #pragma unroll
        for (int off = 16; off; off >>= 1) s += __shfl_xor_sync(0xffffffffu, s, off);
        if (tid == 0) {
            float b = s + inb[o];
            if (p == 0) b *= scale;
            g_bf[o] = b;
        }
    }
}

__global__ void transpose_ow(const float* __restrict__ outw)
{
    int j = blockIdx.x, i = threadIdx.x;
    g_owt[j * E + i] = outw[i * E + j];
}

// ---------------- initial LayerNorm: alpha0 + out[0] ----------------
__global__ void init_ln(const float* __restrict__ mu0, const float* __restrict__ lng,
                        const float* __restrict__ lnb, float* __restrict__ out)
{
    __shared__ float red[10];
    __shared__ float mean_s, rstd_s;
    int k = blockIdx.x, tid = threadIdx.x;      // 320 threads
    float x = mu0[k * E + tid];
    float s = x;
    #pragma unroll
    for (int off = 16; off; off >>= 1) s += __shfl_xor_sync(0xffffffffu, s, off);
    if ((tid & 31) == 0) red[tid >> 5] = s;
    __syncthreads();
    if (tid == 0) { float m = 0; for (int i = 0; i < 10; ++i) m += red[i]; mean_s = m / E; }
    __syncthreads();
    float d = x - mean_s;
    float v = d * d;
    #pragma unroll
    for (int off = 16; off; off >>= 1) v += __shfl_xor_sync(0xffffffffu, v, off);
    if ((tid & 31) == 0) red[tid >> 5] = v;
    __syncthreads();
    if (tid == 0) { float m = 0; for (int i = 0; i < 10; ++i) m += red[i]; rstd_s = rsqrtf(m / E + EPS); }
    __syncthreads();
    float y = d * rstd_s * lng[tid] + lnb[tid];
    g_alpha[k * E + tid] = y;
    out[k * E + tid] = y;
}

// ---------------- per-step fused projection: alpha -> q2, kT, v ----------------
// grid (3, 32) x 320 threads; each thread: 1 output column, 4 alpha rows.
__global__ void proj_kernel(int t)
{
    __shared__ float as[4 * E];
    int tid = threadIdx.x;                  // 0..319
    int o   = blockIdx.x * 320 + tid;       // 0..959
    int k0  = blockIdx.y * 4;
    #pragma unroll
    for (int r = 0; r < 4; ++r) as[r * E + tid] = g_alpha[(k0 + r) * E + tid];
    __syncthreads();
    float a0 = 0, a1 = 0, a2 = 0, a3 = 0;
    #pragma unroll 4
    for (int e = 0; e < E; ++e) {
        float w = g_Wf[e * E3 + o];
        a0 += as[e] * w; a1 += as[E + e] * w; a2 += as[2 * E + e] * w; a3 += as[3 * E + e] * w;
    }
    float b = g_bf[o];
    a0 += b; a1 += b; a2 += b; a3 += b;
    if (o < E) {
        g_q2[(k0 + 0) * E + o] = a0;
        g_q2[(k0 + 1) * E + o] = a1;
        g_q2[(k0 + 2) * E + o] = a2;
        g_q2[(k0 + 3) * E + o] = a3;
    } else if (o < 2 * E) {
        int hh = (o - E) >> 5, d = (o - E) & 31;
        int base = (hh * HD + d) * SMAX + t * KQ + k0;
        g_kT[base + 0] = a0; g_kT[base + 1] = a1; g_kT[base + 2] = a2; g_kT[base + 3] = a3;
    } else {
        int hh = (o - 2 * E) >> 5, d = (o - 2 * E) & 31;
        int row = t * KQ + k0;
        g_v[(hh * SMAX + row + 0) * HD + d] = a0;
        g_v[(hh * SMAX + row + 1) * HD + d] = a1;
        g_v[(hh * SMAX + row + 2) * HD + d] = a2;
        g_v[(hh * SMAX + row + 3) * HD + d] = a3;
    }
}

// ---------------- per-step attention (online softmax, KV-split) ----------------
// grid (16 qgroups, H, split) x 256 threads; 8 queries/block; 256-key chunks.
__global__ __launch_bounds__(256) void attn_kernel(int t, int S, int nchunk, int split)
{
    __shared__ __align__(16) float qsT[HD][8];   // [d][q]
    __shared__ float ps[8][257];                 // scores -> probabilities
    __shared__ float m_sh[8], l_sh[8], corr_sh[8];
    __shared__ float o_sh[8][33];
    int tid = threadIdx.x;
    int qg = blockIdx.x, h = blockIdx.y, sp = blockIdx.z;
    int qbase = qg * 8;

    { int q = tid & 7, d = tid >> 3; qsT[d][q] = g_q2[(qbase + q) * E + h * HD + d]; }
    if (tid < 8) { m_sh[tid] = -1e30f; l_sh[tid] = 0.f; }
    __syncthreads();

    int c0 = (sp * nchunk) / split, c1 = ((sp + 1) * nchunk) / split;
    int jp = tid >> 6, qa = (tid >> 3) & 7, dg = tid & 7;
    float4 acc = make_float4(0.f, 0.f, 0.f, 0.f);
    const float4* qsT4 = (const float4*)qsT;
    const float4* gv4  = (const float4*)g_v;
    int w = tid >> 5, lane = tid & 31;

    for (int c = c0; c < c1; ++c) {
        int base = c * 256;
        // ---- scores: thread = key j = tid ----
        float sc[8];
        #pragma unroll
        for (int q = 0; q < 8; ++q) sc[q] = 0.f;
        const float* kp = &g_kT[(h * HD) * SMAX + base + tid];
        #pragma unroll 8
        for (int d = 0; d < HD; ++d) {
            float kd = kp[d * SMAX];
            float4 qa4 = qsT4[d * 2], qb4 = qsT4[d * 2 + 1];
            sc[0] += qa4.x * kd; sc[1] += qa4.y * kd; sc[2] += qa4.z * kd; sc[3] += qa4.w * kd;
            sc[4] += qb4.x * kd; sc[5] += qb4.y * kd; sc[6] += qb4.z * kd; sc[7] += qb4.w * kd;
        }
        bool valid = (base + tid) < S;
        #pragma unroll
        for (int q = 0; q < 8; ++q) ps[q][tid] = valid ? sc[q] : -1e30f;
        __syncthreads();
        // ---- online softmax: warp w owns query q=w ----
        {
            int q = w;
            float sv[8]; float mx = -1e30f;
            #pragma unroll
            for (int i = 0; i < 8; ++i) { sv[i] = ps[q][lane + 32 * i]; mx = fmaxf(mx, sv[i]); }
            #pragma unroll
            for (int off = 16; off; off >>= 1) mx = fmaxf(mx, __shfl_xor_sync(0xffffffffu, mx, off));
            float mnew = fmaxf(m_sh[q], mx);
            float lsum = 0.f;
            #pragma unroll
            for (int i = 0; i < 8; ++i) {
                float p = __expf(sv[i] - mnew);
                ps[q][lane + 32 * i] = p;
                lsum += p;
            }
            #pragma unroll
            for (int off = 16; off; off >>= 1) lsum += __shfl_xor_sync(0xffffffffu, lsum, off);
            if (lane == 0) {
                float corr = __expf(m_sh[q] - mnew);
                l_sh[q] = l_sh[q] * corr + lsum;
                m_sh[q] = mnew;
                corr_sh[q] = corr;
            }
        }
        __syncthreads();
        // ---- AV: thread = (jp, q, d-group of 4) ----
        float corr = corr_sh[qa];
        acc.x *= corr; acc.y *= corr; acc.z *= corr; acc.w *= corr;
        const float4* vp = &gv4[((h * SMAX + base + jp * 64)) * 8 + dg];
        const float*  pp = &ps[qa][jp * 64];
        #pragma unroll 8
        for (int jj = 0; jj < 64; ++jj) {
            float p = pp[jj];
            float4 vv = vp[jj * 8];
            acc.x += p * vv.x; acc.y += p * vv.y; acc.z += p * vv.z; acc.w += p * vv.w;
        }
        __syncthreads();   // ps reused next chunk
    }

    // reduce acc over the 4 key-partitions
    #pragma unroll
    for (int p = 0; p < 4; ++p) {
        if (jp == p) {
            if (p == 0) {
                o_sh[qa][dg * 4 + 0] = acc.x; o_sh[qa][dg * 4 + 1] = acc.y;
                o_sh[qa][dg * 4 + 2] = acc.z; o_sh[qa][dg * 4 + 3] = acc.w;
            } else {
                o_sh[qa][dg * 4 + 0] += acc.x; o_sh[qa][dg * 4 + 1] += acc.y;
                o_sh[qa][dg * 4 + 2] += acc.z; o_sh[qa][dg * 4 + 3] += acc.w;
            }
        }
        __syncthreads();
    }
    { int q = tid >> 5, d = tid & 31;
      g_po[((sp * H + h) * KQ + qbase + q) * HD + d] = o_sh[q][d]; }
    if (tid < 8) {
        g_pm[(sp * H + h) * KQ + qbase + tid] = m_sh[tid];
        g_pl[(sp * H + h) * KQ + qbase + tid] = l_sh[tid];
    }
}

// ---------------- per-step epilogue: combine splits + out-proj + residual + LN ----------------
// grid 64 x 320 threads; 2 alpha rows per block.
__global__ void epilogue_kernel(int t, int split, const float* __restrict__ outb,
                                const float* __restrict__ lng, const float* __restrict__ lnb,
                                float* __restrict__ out)
{
    __shared__ float o_sh[2][E];
    __shared__ float res[2][E];
    __shared__ float mean2[2], rstd2[2];
    int tid = threadIdx.x;                 // 0..319
    int k0 = blockIdx.x * 2;

    for (int idx = tid; idx < 2 * E; idx += 320) {
        int r = idx / E, e = idx - r * E;
        int hh = e >> 5, d = e & 31;
        int row = k0 + r;
        int i0 = hh * KQ + row;                       // sp = 0
        float m = g_pm[i0], l = g_pl[i0], o = g_po[i0 * HD + d];
        if (split == 2) {
            int i1 = (H * KQ) + hh * KQ + row;        // sp = 1
            float m1 = g_pm[i1], l1 = g_pl[i1], o1 = g_po[i1 * HD + d];
            float M = fmaxf(m, m1);
            float a = __expf(m - M), b1 = __expf(m1 - M);
            o = o * a + o1 * b1;
            l = l * a + l1 * b1;
        }
        o_sh[r][e] = o / l;
    }
    __syncthreads();

    float acc0 = 0.f, acc1 = 0.f;
    int i = tid;
    #pragma unroll 4
    for (int j = 0; j < E; ++j) {
        float w = g_owt[j * E + i];
        acc0 += o_sh[0][j] * w;
        acc1 += o_sh[1][j] * w;
    }
    float ob = outb[i];
    res[0][i] = acc0 + ob + g_alpha[(k0 + 0) * E + i];
    res[1][i] = acc1 + ob + g_alpha[(k0 + 1) * E + i];
    __syncthreads();

    int w = tid >> 5, lane = tid & 31;
    if (w < 2) {
        float s = 0.f;
        for (int ii = lane; ii < E; ii += 32) s += res[w][ii];
        #pragma unroll
        for (int off = 16; off; off >>= 1) s += __shfl_xor_sync(0xffffffffu, s, off);
        float mean = s / E;
        float v = 0.f;
        for (int ii = lane; ii < E; ii += 32) { float d2 = res[w][ii] - mean; v += d2 * d2; }
        #pragma unroll
        for (int off = 16; off; off >>= 1) v += __shfl_xor_sync(0xffffffffu, v, off);
        if (lane == 0) { mean2[w] = mean; rstd2[w] = rsqrtf(v / E + EPS); }
    }
    __syncthreads();
    float gg = lng[tid], bb = lnb[tid];
    #pragma unroll
    for (int r = 0; r < 2; ++r) {
        float y = (res[r][tid] - mean2[r]) * rstd2[r] * gg + bb;
        g_alpha[(k0 + r) * E + tid] = y;
        out[((size_t)(t + 1) * KQ + k0 + r) * E + tid] = y;
    }
}

// ---------------- host ----------------
extern "C" void kernel_launch(void* const* d_in, const int* in_sizes, int n_in,
                              void* d_out, int out_size)
{
    const float* mu0   = (const float*)d_in[0];
    const float* qkvw  = (const float*)d_in[1];
    const float* qkvb  = (const float*)d_in[2];
    const float* inw   = (const float*)d_in[3];
    const float* inb   = (const float*)d_in[4];
    const float* outw  = (const float*)d_in[5];
    const float* outb  = (const float*)d_in[6];
    const float* lng   = (const float*)d_in[7];
    const float* lnb   = (const float*)d_in[8];
    float* out = (float*)d_out;

    fuse_weights<<<E3, E>>>(qkvw, qkvb, inw, inb);
    transpose_ow<<<E, E>>>(outw);
    init_ln<<<KQ, E>>>(mu0, lng, lnb, out);

    for (int t = 0; t < TM1; ++t) {
        proj_kernel<<<dim3(3, 32), 320>>>(t);
        int S = (t + 1) * KQ;
        int nchunk = (S + 255) / 256;
        int split = (nchunk >= 2) ? 2 : 1;
        attn_kernel<<<dim3(16, H, split), 256>>>(t, S, nchunk, split);
        epilogue_kernel<<<64, 320>>>(t, split, outb, lng, lnb, out);
    }
}

// round 3
// speedup vs baseline: 2.2045x; 2.2045x over previous
#include <cuda_runtime.h>
#include <math.h>

#define E   320
#define E3  960
#define KQ  128
#define TT  256
#define TM1 255
#define H   10
#define HD  32
#define SMAX 32768
#define EPS 1e-5f
#define CH  64          // keys per chunk
#define MAXSPLIT 30

// ---------------- device scratch ----------------
__device__ float g_Wf[E * E3];
__device__ float g_bf[E3];
__device__ float g_owt[E * E];
__device__ float g_alpha[KQ * E];
__device__ float g_q2[KQ * E];
__device__ float g_kT[H * HD * SMAX];            // [h][d][s]
__device__ float g_v [H * SMAX * HD];            // [h][s][d]
__device__ float g_pm[MAXSPLIT * H * KQ];
__device__ float g_pl[MAXSPLIT * H * KQ];
__device__ float g_po[MAXSPLIT * H * KQ * HD];

// ---------------- one-time weight fusion ----------------
__global__ void fuse_weights(const float* __restrict__ qkvw, const float* __restrict__ qkvb,
                             const float* __restrict__ inw,  const float* __restrict__ inb)
{
    __shared__ float wrow[E];
    int o = blockIdx.x, p = o / E, tid = threadIdx.x;
    wrow[tid] = inw[o * E + tid];
    __syncthreads();
    const float scale = 0.17677669529663687f;
    float acc = 0.f;
    int e = tid;
    #pragma unroll 4
    for (int j = 0; j < E; ++j) acc += wrow[j] * qkvw[(p * E + j) * E + e];
    if (p == 0) acc *= scale;
    g_Wf[e * E3 + o] = acc;
    if (tid < 32) {
        float s = 0.f;
        for (int j = tid; j < E; j += 32) s += wrow[j] * qkvb[p * E + j];
        #pragma unroll
        for (int off = 16; off; off >>= 1) s += __shfl_xor_sync(0xffffffffu, s, off);
        if (tid == 0) { float b = s + inb[o]; if (p == 0) b *= scale; g_bf[o] = b; }
    }
}

__global__ void transpose_ow(const float* __restrict__ outw)
{
    int j = blockIdx.x, i = threadIdx.x;
    g_owt[j * E + i] = outw[i * E + j];
}

// ---------------- initial LayerNorm ----------------
__global__ void init_ln(const float* __restrict__ mu0, const float* __restrict__ lng,
                        const float* __restrict__ lnb, float* __restrict__ out)
{
    __shared__ float red[10];
    __shared__ float mean_s, rstd_s;
    int k = blockIdx.x, tid = threadIdx.x;
    float x = mu0[k * E + tid];
    float s = x;
    #pragma unroll
    for (int off = 16; off; off >>= 1) s += __shfl_xor_sync(0xffffffffu, s, off);
    if ((tid & 31) == 0) red[tid >> 5] = s;
    __syncthreads();
    if (tid == 0) { float m = 0; for (int i = 0; i < 10; ++i) m += red[i]; mean_s = m / E; }
    __syncthreads();
    float d = x - mean_s;
    float v = d * d;
    #pragma unroll
    for (int off = 16; off; off >>= 1) v += __shfl_xor_sync(0xffffffffu, v, off);
    if ((tid & 31) == 0) red[tid >> 5] = v;
    __syncthreads();
    if (tid == 0) { float m = 0; for (int i = 0; i < 10; ++i) m += red[i]; rstd_s = rsqrtf(m / E + EPS); }
    __syncthreads();
    float y = d * rstd_s * lng[tid] + lnb[tid];
    g_alpha[k * E + tid] = y;
    out[k * E + tid] = y;
}

// ---------------- per-step fused projection ----------------
// grid (4, 64) x 240 threads; thread: 1 col, 2 rows; unroll 8 -> 8 loads in flight.
__global__ __launch_bounds__(240) void proj_kernel(int t)
{
    __shared__ float as[2 * E];
    int tid = threadIdx.x;
    int o = blockIdx.x * 240 + tid;
    int k0 = blockIdx.y * 2;
    for (int i = tid; i < 2 * E; i += 240) as[i] = g_alpha[k0 * E + i];
    __syncthreads();
    float a0 = 0.f, a1 = 0.f;
    #pragma unroll 8
    for (int e = 0; e < E; ++e) {
        float w = g_Wf[e * E3 + o];
        a0 += as[e] * w; a1 += as[E + e] * w;
    }
    float b = g_bf[o];
    a0 += b; a1 += b;
    if (o < E) {
        g_q2[(k0 + 0) * E + o] = a0;
        g_q2[(k0 + 1) * E + o] = a1;
    } else if (o < 2 * E) {
        int hh = (o - E) >> 5, d = (o - E) & 31;
        int base = (hh * HD + d) * SMAX + t * KQ + k0;
        g_kT[base] = a0; g_kT[base + 1] = a1;
    } else {
        int hh = (o - 2 * E) >> 5, d = (o - 2 * E) & 31;
        int row = t * KQ + k0;
        g_v[(hh * SMAX + row) * HD + d] = a0;
        g_v[(hh * SMAX + row + 1) * HD + d] = a1;
    }
}

// ---------------- attention: grid (H, split) x 256 thr, all 128 queries per block ----------------
// smem: qsT 16KB | ks 8KB | vs 8KB | psT 32KB  = 64KB dynamic
__global__ __launch_bounds__(256, 2) void attn_kernel(int t, int nchunk, int split)
{
    extern __shared__ float sm[];
    float*  qsT = sm;                    // [32 d][32 float4], slot = d*32 + (c ^ d)
    float*  ks  = sm + 4096;             // [32 d][64 k]
    float*  vs  = ks + 2048;             // [64 k][32 d]
    float*  psT = vs + 2048;             // [64 k][32 float4], slot = k*32 + (c ^ 2*(k>>2))
    float4* qsT4 = (float4*)qsT;
    const float4* ks4 = (const float4*)ks;
    const float2* vs2 = (const float2*)vs;
    float4* psT4 = (float4*)psT;

    int tid = threadIdx.x;
    int h = blockIdx.x, sp = blockIdx.y;
    int qg = tid >> 4;            // 0..15 : q rows 8*qg..8*qg+7
    int ky = tid & 15;            // 0..15 : k cols 4*ky..4*ky+3, d = 2*ky..2*ky+1

    // load Q tile (swizzled)
    {
        int d = tid & 31, qb = tid >> 5;
        #pragma unroll
        for (int it = 0; it < 16; ++it) {
            int q = qb + it * 8;
            float val = g_q2[q * E + h * HD + d];
            int c = q >> 2;
            qsT[(d * 32 + (c ^ d)) * 4 + (q & 3)] = val;
        }
    }

    float m[8], l[8], c0r[8], c1r[8];
    #pragma unroll
    for (int i = 0; i < 8; ++i) { m[i] = -1e30f; l[i] = 0.f; c0r[i] = 0.f; c1r[i] = 0.f; }

    int cA = (sp * nchunk) / split, cB = ((sp + 1) * nchunk) / split;

    for (int c = cA; c < cB; ++c) {
        int base = c * CH;
        __syncthreads();   // prev AV done (and qsT ready on first iter)
        // load K chunk: ks[d][j]
        {
            int j = tid & 63, dq = tid >> 6;
            #pragma unroll
            for (int dd = 0; dd < 8; ++dd) {
                int d = dq + dd * 4;
                ks[d * 64 + j] = g_kT[(h * HD + d) * SMAX + base + j];
            }
        }
        // load V chunk: vs[k][d]
        {
            int d = tid & 31, kq2 = tid >> 5;
            #pragma unroll
            for (int kk = 0; kk < 8; ++kk) {
                int k = kq2 + kk * 8;
                vs[k * 32 + d] = g_v[(h * SMAX + base + k) * HD + d];
            }
        }
        __syncthreads();

        // ---- scores: 8q x 4k per thread ----
        float sc[8][4];
        #pragma unroll
        for (int i = 0; i < 8; ++i)
            #pragma unroll
            for (int j = 0; j < 4; ++j) sc[i][j] = 0.f;
        #pragma unroll
        for (int d = 0; d < HD; ++d) {
            float4 kv = ks4[d * 16 + ky];
            float4 qa = qsT4[d * 32 + ((2 * qg) ^ d)];
            float4 qb = qsT4[d * 32 + ((2 * qg + 1) ^ d)];
            float kf[4] = {kv.x, kv.y, kv.z, kv.w};
            float qf[8] = {qa.x, qa.y, qa.z, qa.w, qb.x, qb.y, qb.z, qb.w};
            #pragma unroll
            for (int i = 0; i < 8; ++i)
                #pragma unroll
                for (int j = 0; j < 4; ++j) sc[i][j] += qf[i] * kf[j];
        }

        // ---- online softmax (reduce across the 16-lane ky group) ----
        float corr[8];
        #pragma unroll
        for (int i = 0; i < 8; ++i) {
            float mx = fmaxf(fmaxf(sc[i][0], sc[i][1]), fmaxf(sc[i][2], sc[i][3]));
            #pragma unroll
            for (int off = 8; off; off >>= 1) mx = fmaxf(mx, __shfl_xor_sync(0xffffffffu, mx, off));
            float mnew = fmaxf(m[i], mx);
            corr[i] = __expf(m[i] - mnew);
            float ls = 0.f;
            #pragma unroll
            for (int j = 0; j < 4; ++j) { float p = __expf(sc[i][j] - mnew); sc[i][j] = p; ls += p; }
            #pragma unroll
            for (int off = 8; off; off >>= 1) ls += __shfl_xor_sync(0xffffffffu, ls, off);
            l[i] = l[i] * corr[i] + ls;
            m[i] = mnew;
            c0r[i] *= corr[i];
            c1r[i] *= corr[i];
        }
        // write probs (swizzled): cols for qg at slot (2*qg)^(2*ky), +1
        {
            int s0 = (2 * qg) ^ (2 * ky);
            #pragma unroll
            for (int j = 0; j < 4; ++j) {
                int k = 4 * ky + j;
                psT4[k * 32 + s0]     = make_float4(sc[0][j], sc[1][j], sc[2][j], sc[3][j]);
                psT4[k * 32 + s0 + 1] = make_float4(sc[4][j], sc[5][j], sc[6][j], sc[7][j]);
            }
        }
        __syncthreads();

        // ---- AV: out[8q][2d] per thread ----
        #pragma unroll 4
        for (int k = 0; k < CH; ++k) {
            int s0 = (2 * qg) ^ (2 * (k >> 2));
            float4 pa = psT4[k * 32 + s0];
            float4 pb = psT4[k * 32 + s0 + 1];
            float2 vv = vs2[k * 16 + ky];
            float pf[8] = {pa.x, pa.y, pa.z, pa.w, pb.x, pb.y, pb.z, pb.w};
            #pragma unroll
            for (int i = 0; i < 8; ++i) {
                c0r[i] += pf[i] * vv.x;
                c1r[i] += pf[i] * vv.y;
            }
        }
    }

    // write partials
    int pbase = (sp * H + h) * KQ;
    #pragma unroll
    for (int i = 0; i < 8; ++i) {
        int q = 8 * qg + i;
        float2* po2 = (float2*)&g_po[(pbase + q) * HD + 2 * ky];
        *po2 = make_float2(c0r[i], c1r[i]);
    }
    if (ky == 0) {
        #pragma unroll
        for (int i = 0; i < 8; ++i) {
            int q = 8 * qg + i;
            g_pm[pbase + q] = m[i];
            g_pl[pbase + q] = l[i];
        }
    }
}

// ---------------- epilogue: combine splits + out-proj + residual + LN ----------------
__global__ __launch_bounds__(320) void epilogue_kernel(int t, int split, const float* __restrict__ outb,
                                const float* __restrict__ lng, const float* __restrict__ lnb,
                                float* __restrict__ out)
{
    __shared__ float o_sh[2][E];
    __shared__ float res[2][E];
    __shared__ float ws[2][H][MAXSPLIT];
    __shared__ float lcinv[2][H];
    __shared__ float mean2[2], rstd2[2];
    int tid = threadIdx.x;
    int k0 = blockIdx.x * 2;

    if (tid < 2 * H) {
        int r = tid / H, hh = tid % H;
        int row = k0 + r;
        float M = -1e30f;
        for (int sp = 0; sp < split; ++sp)
            M = fmaxf(M, g_pm[(sp * H + hh) * KQ + row]);
        float lsum = 0.f;
        for (int sp = 0; sp < split; ++sp) {
            float w = __expf(g_pm[(sp * H + hh) * KQ + row] - M);
            ws[r][hh][sp] = w;
            lsum += w * g_pl[(sp * H + hh) * KQ + row];
        }
        lcinv[r][hh] = 1.f / lsum;
    }
    __syncthreads();

    for (int idx = tid; idx < 2 * E; idx += 320) {
        int r = idx / E, e = idx - r * E;
        int hh = e >> 5, d = e & 31, row = k0 + r;
        float o = 0.f;
        for (int sp = 0; sp < split; ++sp)
            o += ws[r][hh][sp] * g_po[((sp * H + hh) * KQ + row) * HD + d];
        o_sh[r][e] = o * lcinv[r][hh];
    }
    __syncthreads();

    float acc0 = 0.f, acc1 = 0.f;
    int i = tid;
    #pragma unroll 4
    for (int j = 0; j < E; ++j) {
        float w = g_owt[j * E + i];
        acc0 += o_sh[0][j] * w;
        acc1 += o_sh[1][j] * w;
    }
    float ob = outb[i];
    res[0][i] = acc0 + ob + g_alpha[(k0 + 0) * E + i];
    res[1][i] = acc1 + ob + g_alpha[(k0 + 1) * E + i];
    __syncthreads();

    int w = tid >> 5, lane = tid & 31;
    if (w < 2) {
        float s = 0.f;
        for (int ii = lane; ii < E; ii += 32) s += res[w][ii];
        #pragma unroll
        for (int off = 16; off; off >>= 1) s += __shfl_xor_sync(0xffffffffu, s, off);
        float mean = s / E;
        float v = 0.f;
        for (int ii = lane; ii < E; ii += 32) { float d2 = res[w][ii] - mean; v += d2 * d2; }
        #pragma unroll
        for (int off = 16; off; off >>= 1) v += __shfl_xor_sync(0xffffffffu, v, off);
        if (lane == 0) { mean2[w] = mean; rstd2[w] = rsqrtf(v / E + EPS); }
    }
    __syncthreads();
    float gg = lng[tid], bb = lnb[tid];
    #pragma unroll
    for (int r = 0; r < 2; ++r) {
        float y = (res[r][tid] - mean2[r]) * rstd2[r] * gg + bb;
        g_alpha[(k0 + r) * E + tid] = y;
        out[((size_t)(t + 1) * KQ + k0 + r) * E + tid] = y;
    }
}

// ---------------- host ----------------
extern "C" void kernel_launch(void* const* d_in, const int* in_sizes, int n_in,
                              void* d_out, int out_size)
{
    const float* mu0   = (const float*)d_in[0];
    const float* qkvw  = (const float*)d_in[1];
    const float* qkvb  = (const float*)d_in[2];
    const float* inw   = (const float*)d_in[3];
    const float* inb   = (const float*)d_in[4];
    const float* outw  = (const float*)d_in[5];
    const float* outb  = (const float*)d_in[6];
    const float* lng   = (const float*)d_in[7];
    const float* lnb   = (const float*)d_in[8];
    float* out = (float*)d_out;

    cudaFuncSetAttribute(attn_kernel, cudaFuncAttributeMaxDynamicSharedMemorySize, 65536);

    fuse_weights<<<E3, E>>>(qkvw, qkvb, inw, inb);
    transpose_ow<<<E, E>>>(outw);
    init_ln<<<KQ, E>>>(mu0, lng, lnb, out);

    for (int t = 0; t < TM1; ++t) {
        proj_kernel<<<dim3(4, 64), 240>>>(t);
        int nchunk = 2 * (t + 1);                 // S = (t+1)*128, CH=64
        int split = (nchunk < MAXSPLIT) ? nchunk : MAXSPLIT;
        attn_kernel<<<dim3(H, split), 256, 65536>>>(t, nchunk, split);
        epilogue_kernel<<<64, 320>>>(t, split, outb, lng, lnb, out);
    }
}

// round 4
// speedup vs baseline: 2.3371x; 1.0601x over previous
#include <cuda_runtime.h>
#include <math.h>

#define E   320
#define E3  960
#define KQ  128
#define TT  256
#define TM1 255
#define H   10
#define HD  32
#define SMAX 32768
#define EPS 1e-5f
#define CH  64
#define MAXSPLIT 30

typedef unsigned long long u64;

__device__ __forceinline__ u64 pk2(float x, float y) {
    u64 r; asm("mov.b64 %0,{%1,%2};" : "=l"(r) : "f"(x), "f"(y)); return r;
}
__device__ __forceinline__ float2 upk2(u64 a) {
    float2 r; asm("mov.b64 {%0,%1},%2;" : "=f"(r.x), "=f"(r.y) : "l"(a)); return r;
}
__device__ __forceinline__ u64 f2fma(u64 a, u64 b, u64 c) {
    u64 d; asm("fma.rn.f32x2 %0,%1,%2,%3;" : "=l"(d) : "l"(a), "l"(b), "l"(c)); return d;
}
__device__ __forceinline__ u64 f2mul(u64 a, u64 b) {
    u64 d; asm("mul.rn.f32x2 %0,%1,%2;" : "=l"(d) : "l"(a), "l"(b)); return d;
}

// ---------------- device scratch ----------------
__device__ float g_Wf[E * E3];
__device__ float g_bf[E3];
__device__ float g_owt[E * E];
__device__ float g_alpha[KQ * E];
__device__ float g_q2[KQ * E];
__device__ float g_kT[H * HD * SMAX];            // [h][d][s]
__device__ float g_v [H * SMAX * HD];            // [h][s][d]
__device__ float g_pm[MAXSPLIT * H * KQ];
__device__ float g_pl[MAXSPLIT * H * KQ];
__device__ float g_po[MAXSPLIT * H * KQ * HD];

// ---------------- one-time weight fusion ----------------
__global__ void fuse_weights(const float* __restrict__ qkvw, const float* __restrict__ qkvb,
                             const float* __restrict__ inw,  const float* __restrict__ inb)
{
    __shared__ float wrow[E];
    int o = blockIdx.x, p = o / E, tid = threadIdx.x;
    wrow[tid] = inw[o * E + tid];
    __syncthreads();
    const float scale = 0.17677669529663687f;
    float acc = 0.f;
    int e = tid;
    #pragma unroll 4
    for (int j = 0; j < E; ++j) acc += wrow[j] * qkvw[(p * E + j) * E + e];
    if (p == 0) acc *= scale;
    g_Wf[e * E3 + o] = acc;
    if (tid < 32) {
        float s = 0.f;
        for (int j = tid; j < E; j += 32) s += wrow[j] * qkvb[p * E + j];
        #pragma unroll
        for (int off = 16; off; off >>= 1) s += __shfl_xor_sync(0xffffffffu, s, off);
        if (tid == 0) { float b = s + inb[o]; if (p == 0) b *= scale; g_bf[o] = b; }
    }
}

__global__ void transpose_ow(const float* __restrict__ outw)
{
    int j = blockIdx.x, i = threadIdx.x;
    g_owt[j * E + i] = outw[i * E + j];
}

// ---------------- initial LayerNorm ----------------
__global__ void init_ln(const float* __restrict__ mu0, const float* __restrict__ lng,
                        const float* __restrict__ lnb, float* __restrict__ out)
{
    __shared__ float red[10];
    __shared__ float mean_s, rstd_s;
    int k = blockIdx.x, tid = threadIdx.x;
    float x = mu0[k * E + tid];
    float s = x;
    #pragma unroll
    for (int off = 16; off; off >>= 1) s += __shfl_xor_sync(0xffffffffu, s, off);
    if ((tid & 31) == 0) red[tid >> 5] = s;
    __syncthreads();
    if (tid == 0) { float m = 0; for (int i = 0; i < 10; ++i) m += red[i]; mean_s = m / E; }
    __syncthreads();
    float d = x - mean_s;
    float v = d * d;
    #pragma unroll
    for (int off = 16; off; off >>= 1) v += __shfl_xor_sync(0xffffffffu, v, off);
    if ((tid & 31) == 0) red[tid >> 5] = v;
    __syncthreads();
    if (tid == 0) { float m = 0; for (int i = 0; i < 10; ++i) m += red[i]; rstd_s = rsqrtf(m / E + EPS); }
    __syncthreads();
    float y = d * rstd_s * lng[tid] + lnb[tid];
    g_alpha[k * E + tid] = y;
    out[k * E + tid] = y;
}

// ---------------- per-step fused projection (packed f32x2, 2 rows/thread) ----------------
__global__ __launch_bounds__(240) void proj_kernel(int t)
{
    __shared__ u64 as2[E];          // (row0[e], row1[e]) packed
    int tid = threadIdx.x;
    int o = blockIdx.x * 240 + tid;
    int k0 = blockIdx.y * 2;
    for (int i = tid; i < E; i += 240)
        as2[i] = pk2(g_alpha[k0 * E + i], g_alpha[(k0 + 1) * E + i]);
    __syncthreads();
    u64 acc = 0ull;
    #pragma unroll 16
    for (int e = 0; e < E; ++e) {
        float w = g_Wf[e * E3 + o];
        acc = f2fma(as2[e], pk2(w, w), acc);
    }
    float2 ar = upk2(acc);
    float b = g_bf[o];
    float a0 = ar.x + b, a1 = ar.y + b;
    if (o < E) {
        g_q2[(k0 + 0) * E + o] = a0;
        g_q2[(k0 + 1) * E + o] = a1;
    } else if (o < 2 * E) {
        int hh = (o - E) >> 5, d = (o - E) & 31;
        int base = (hh * HD + d) * SMAX + t * KQ + k0;
        g_kT[base] = a0; g_kT[base + 1] = a1;
    } else {
        int hh = (o - 2 * E) >> 5, d = (o - 2 * E) & 31;
        int row = t * KQ + k0;
        g_v[(hh * SMAX + row) * HD + d] = a0;
        g_v[(hh * SMAX + row + 1) * HD + d] = a1;
    }
}

// ---------------- attention: grid (H, split) x 256 thr, packed-f32x2 math ----------------
// smem: qsT 16KB | ks 8KB | vs 8KB | psT 32KB  = 64KB dynamic
__global__ __launch_bounds__(256, 2) void attn_kernel(int t, int nchunk, int split)
{
    extern __shared__ float sm[];
    float*  qsT = sm;                    // [32 d][32 float4], slot = d*32 + (c ^ d)
    float*  ks  = sm + 4096;             // [32 d][64 k]
    float*  vs  = ks + 2048;             // [64 k][32 d]
    float*  psT = vs + 2048;             // [64 k][32 float4], slot swizzled
    const ulonglong2* qsU2 = (const ulonglong2*)qsT;
    const float4* ks4 = (const float4*)ks;
    const float2* vs2 = (const float2*)vs;
    float4* psT4 = (float4*)psT;
    const ulonglong2* psU2 = (const ulonglong2*)psT;

    int tid = threadIdx.x;
    int h = blockIdx.x, sp = blockIdx.y;
    int qg = tid >> 4;            // 0..15 : q rows 8*qg..8*qg+7
    int ky = tid & 15;            // 0..15 : k cols 4*ky..+3, d = 2*ky..+1

    // load Q tile (swizzled)
    {
        int d = tid & 31, qb = tid >> 5;
        #pragma unroll
        for (int it = 0; it < 16; ++it) {
            int q = qb + it * 8;
            float val = g_q2[q * E + h * HD + d];
            int c = q >> 2;
            qsT[(d * 32 + (c ^ d)) * 4 + (q & 3)] = val;
        }
    }

    float m[8], l[8];
    u64 acc_pk[4][2];                    // [qpair][d0/d1]
    #pragma unroll
    for (int i = 0; i < 8; ++i) { m[i] = -1e30f; l[i] = 0.f; }
    #pragma unroll
    for (int i = 0; i < 4; ++i) { acc_pk[i][0] = 0ull; acc_pk[i][1] = 0ull; }

    int cA = (sp * nchunk) / split, cB = ((sp + 1) * nchunk) / split;

    for (int c = cA; c < cB; ++c) {
        int base = c * CH;
        __syncthreads();
        {   // load K chunk: ks[d][j]
            int j = tid & 63, dq = tid >> 6;
            #pragma unroll
            for (int dd = 0; dd < 8; ++dd) {
                int d = dq + dd * 4;
                ks[d * 64 + j] = g_kT[(h * HD + d) * SMAX + base + j];
            }
        }
        {   // load V chunk: vs[k][d]
            int d = tid & 31, kq2 = tid >> 5;
            #pragma unroll
            for (int kk = 0; kk < 8; ++kk) {
                int k = kq2 + kk * 8;
                vs[k * 32 + d] = g_v[(h * SMAX + base + k) * HD + d];
            }
        }
        __syncthreads();

        // ---- scores: packed over query pairs, 4 qpairs x 4 keys ----
        u64 sc2[4][4];
        #pragma unroll
        for (int i = 0; i < 4; ++i)
            #pragma unroll
            for (int j = 0; j < 4; ++j) sc2[i][j] = 0ull;
        #pragma unroll
        for (int d = 0; d < HD; ++d) {
            float4 kv = ks4[d * 16 + ky];
            u64 kp0 = pk2(kv.x, kv.x), kp1 = pk2(kv.y, kv.y);
            u64 kp2 = pk2(kv.z, kv.z), kp3 = pk2(kv.w, kv.w);
            ulonglong2 qa = qsU2[d * 32 + ((2 * qg) ^ d)];     // (q0,q1),(q2,q3)
            ulonglong2 qb = qsU2[d * 32 + ((2 * qg + 1) ^ d)]; // (q4,q5),(q6,q7)
            sc2[0][0] = f2fma(qa.x, kp0, sc2[0][0]);
            sc2[0][1] = f2fma(qa.x, kp1, sc2[0][1]);
            sc2[0][2] = f2fma(qa.x, kp2, sc2[0][2]);
            sc2[0][3] = f2fma(qa.x, kp3, sc2[0][3]);
            sc2[1][0] = f2fma(qa.y, kp0, sc2[1][0]);
            sc2[1][1] = f2fma(qa.y, kp1, sc2[1][1]);
            sc2[1][2] = f2fma(qa.y, kp2, sc2[1][2]);
            sc2[1][3] = f2fma(qa.y, kp3, sc2[1][3]);
            sc2[2][0] = f2fma(qb.x, kp0, sc2[2][0]);
            sc2[2][1] = f2fma(qb.x, kp1, sc2[2][1]);
            sc2[2][2] = f2fma(qb.x, kp2, sc2[2][2]);
            sc2[2][3] = f2fma(qb.x, kp3, sc2[2][3]);
            sc2[3][0] = f2fma(qb.y, kp0, sc2[3][0]);
            sc2[3][1] = f2fma(qb.y, kp1, sc2[3][1]);
            sc2[3][2] = f2fma(qb.y, kp2, sc2[3][2]);
            sc2[3][3] = f2fma(qb.y, kp3, sc2[3][3]);
        }
        // unpack to per-query scores
        float sc[8][4];
        #pragma unroll
        for (int i2 = 0; i2 < 4; ++i2)
            #pragma unroll
            for (int j = 0; j < 4; ++j) {
                float2 tv = upk2(sc2[i2][j]);
                sc[2 * i2][j] = tv.x; sc[2 * i2 + 1][j] = tv.y;
            }

        // ---- online softmax (reduce across 16-lane ky group) ----
        float corr[8];
        #pragma unroll
        for (int i = 0; i < 8; ++i) {
            float mx = fmaxf(fmaxf(sc[i][0], sc[i][1]), fmaxf(sc[i][2], sc[i][3]));
            #pragma unroll
            for (int off = 8; off; off >>= 1) mx = fmaxf(mx, __shfl_xor_sync(0xffffffffu, mx, off));
            float mnew = fmaxf(m[i], mx);
            corr[i] = __expf(m[i] - mnew);
            float ls = 0.f;
            #pragma unroll
            for (int j = 0; j < 4; ++j) { float p = __expf(sc[i][j] - mnew); sc[i][j] = p; ls += p; }
            #pragma unroll
            for (int off = 8; off; off >>= 1) ls += __shfl_xor_sync(0xffffffffu, ls, off);
            l[i] = l[i] * corr[i] + ls;
            m[i] = mnew;
        }
        {   // write probs (swizzled)
            int s0 = (2 * qg) ^ (2 * ky);
            #pragma unroll
            for (int j = 0; j < 4; ++j) {
                int k = 4 * ky + j;
                psT4[k * 32 + s0]     = make_float4(sc[0][j], sc[1][j], sc[2][j], sc[3][j]);
                psT4[k * 32 + s0 + 1] = make_float4(sc[4][j], sc[5][j], sc[6][j], sc[7][j]);
            }
        }
        // rescale accumulators (packed corr pairs)
        #pragma unroll
        for (int i2 = 0; i2 < 4; ++i2) {
            u64 cp = pk2(corr[2 * i2], corr[2 * i2 + 1]);
            acc_pk[i2][0] = f2mul(acc_pk[i2][0], cp);
            acc_pk[i2][1] = f2mul(acc_pk[i2][1], cp);
        }
        __syncthreads();

        // ---- AV: packed over query pairs; thread covers 8q x 2d ----
        #pragma unroll 4
        for (int k = 0; k < CH; ++k) {
            int s0 = (2 * qg) ^ (2 * (k >> 2));
            ulonglong2 pa = psU2[k * 32 + s0];       // (p0,p1),(p2,p3)
            ulonglong2 pb = psU2[k * 32 + s0 + 1];   // (p4,p5),(p6,p7)
            float2 vv = vs2[k * 16 + ky];
            u64 vx = pk2(vv.x, vv.x), vy = pk2(vv.y, vv.y);
            acc_pk[0][0] = f2fma(pa.x, vx, acc_pk[0][0]);
            acc_pk[0][1] = f2fma(pa.x, vy, acc_pk[0][1]);
            acc_pk[1][0] = f2fma(pa.y, vx, acc_pk[1][0]);
            acc_pk[1][1] = f2fma(pa.y, vy, acc_pk[1][1]);
            acc_pk[2][0] = f2fma(pb.x, vx, acc_pk[2][0]);
            acc_pk[2][1] = f2fma(pb.x, vy, acc_pk[2][1]);
            acc_pk[3][0] = f2fma(pb.y, vx, acc_pk[3][0]);
            acc_pk[3][1] = f2fma(pb.y, vy, acc_pk[3][1]);
        }
    }

    // write partials
    int pbase = (sp * H + h) * KQ;
    #pragma unroll
    for (int i2 = 0; i2 < 4; ++i2) {
        float2 t0 = upk2(acc_pk[i2][0]);   // (q even, q odd) for dim d0
        float2 t1 = upk2(acc_pk[i2][1]);   // for dim d1
        int q0 = 8 * qg + 2 * i2;
        float2* po2a = (float2*)&g_po[(pbase + q0) * HD + 2 * ky];
        float2* po2b = (float2*)&g_po[(pbase + q0 + 1) * HD + 2 * ky];
        *po2a = make_float2(t0.x, t1.x);
        *po2b = make_float2(t0.y, t1.y);
    }
    if (ky == 0) {
        #pragma unroll
        for (int i = 0; i < 8; ++i) {
            int q = 8 * qg + i;
            g_pm[pbase + q] = m[i];
            g_pl[pbase + q] = l[i];
        }
    }
}

// ---------------- epilogue: combine splits + out-proj + residual + LN ----------------
__global__ __launch_bounds__(320) void epilogue_kernel(int t, int split, const float* __restrict__ outb,
                                const float* __restrict__ lng, const float* __restrict__ lnb,
                                float* __restrict__ out)
{
    __shared__ float o_sh[2][E];
    __shared__ float res[2][E];
    __shared__ float ws[2][H][MAXSPLIT];
    __shared__ float lcinv[2][H];
    __shared__ float mean2[2], rstd2[2];
    int tid = threadIdx.x;
    int k0 = blockIdx.x * 2;

    if (tid < 2 * H) {
        int r = tid / H, hh = tid % H;
        int row = k0 + r;
        float M = -1e30f;
        for (int sp = 0; sp < split; ++sp)
            M = fmaxf(M, g_pm[(sp * H + hh) * KQ + row]);
        float lsum = 0.f;
        for (int sp = 0; sp < split; ++sp) {
            float w = __expf(g_pm[(sp * H + hh) * KQ + row] - M);
            ws[r][hh][sp] = w;
            lsum += w * g_pl[(sp * H + hh) * KQ + row];
        }
        lcinv[r][hh] = 1.f / lsum;
    }
    __syncthreads();

    for (int idx = tid; idx < 2 * E; idx += 320) {
        int r = idx / E, e = idx - r * E;
        int hh = e >> 5, d = e & 31, row = k0 + r;
        float o = 0.f;
        for (int sp = 0; sp < split; ++sp)
            o += ws[r][hh][sp] * g_po[((sp * H + hh) * KQ + row) * HD + d];
        o_sh[r][e] = o * lcinv[r][hh];
    }
    __syncthreads();

    u64 acc = 0ull;
    int i = tid;
    #pragma unroll 4
    for (int j = 0; j < E; ++j) {
        float w = g_owt[j * E + i];
        acc = f2fma(pk2(o_sh[0][j], o_sh[1][j]), pk2(w, w), acc);
    }
    float2 av = upk2(acc);
    float ob = outb[i];
    res[0][i] = av.x + ob + g_alpha[(k0 + 0) * E + i];
    res[1][i] = av.y + ob + g_alpha[(k0 + 1) * E + i];
    __syncthreads();

    int w = tid >> 5, lane = tid & 31;
    if (w < 2) {
        float s = 0.f;
        for (int ii = lane; ii < E; ii += 32) s += res[w][ii];
        #pragma unroll
        for (int off = 16; off; off >>= 1) s += __shfl_xor_sync(0xffffffffu, s, off);
        float mean = s / E;
        float v = 0.f;
        for (int ii = lane; ii < E; ii += 32) { float d2 = res[w][ii] - mean; v += d2 * d2; }
        #pragma unroll
        for (int off = 16; off; off >>= 1) v += __shfl_xor_sync(0xffffffffu, v, off);
        if (lane == 0) { mean2[w] = mean; rstd2[w] = rsqrtf(v / E + EPS); }
    }
    __syncthreads();
    float gg = lng[tid], bb = lnb[tid];
    #pragma unroll
    for (int r = 0; r < 2; ++r) {
        float y = (res[r][tid] - mean2[r]) * rstd2[r] * gg + bb;
        g_alpha[(k0 + r) * E + tid] = y;
        out[((size_t)(t + 1) * KQ + k0 + r) * E + tid] = y;
    }
}

// ---------------- host ----------------
extern "C" void kernel_launch(void* const* d_in, const int* in_sizes, int n_in,
                              void* d_out, int out_size)
{
    const float* mu0   = (const float*)d_in[0];
    const float* qkvw  = (const float*)d_in[1];
    const float* qkvb  = (const float*)d_in[2];
    const float* inw   = (const float*)d_in[3];
    const float* inb   = (const float*)d_in[4];
    const float* outw  = (const float*)d_in[5];
    const float* outb  = (const float*)d_in[6];
    const float* lng   = (const float*)d_in[7];
    const float* lnb   = (const float*)d_in[8];
    float* out = (float*)d_out;

    cudaFuncSetAttribute(attn_kernel, cudaFuncAttributeMaxDynamicSharedMemorySize, 65536);

    fuse_weights<<<E3, E>>>(qkvw, qkvb, inw, inb);
    transpose_ow<<<E, E>>>(outw);
    init_ln<<<KQ, E>>>(mu0, lng, lnb, out);

    for (int t = 0; t < TM1; ++t) {
        proj_kernel<<<dim3(4, 64), 240>>>(t);
        int nchunk = 2 * (t + 1);
        int split = (nchunk < MAXSPLIT) ? nchunk : MAXSPLIT;
        attn_kernel<<<dim3(H, split), 256, 65536>>>(t, nchunk, split);
        epilogue_kernel<<<64, 320>>>(t, split, outb, lng, lnb, out);
    }
}

// round 5
// speedup vs baseline: 4.0183x; 1.7194x over previous
#include <cuda_runtime.h>
#include <cuda_bf16.h>
#include <math.h>

#define E   320
#define E3  960
#define KQ  128
#define TT  256
#define TM1 255
#define H   10
#define HD  32
#define SMAX 32768
#define EPS 1e-5f
#define CH  64
#define MAXSPLIT 30

typedef unsigned long long u64;
typedef unsigned int u32;

__device__ __forceinline__ u64 pk2(float x, float y) {
    u64 r; asm("mov.b64 %0,{%1,%2};" : "=l"(r) : "f"(x), "f"(y)); return r;
}
__device__ __forceinline__ float2 upk2(u64 a) {
    float2 r; asm("mov.b64 {%0,%1},%2;" : "=f"(r.x), "=f"(r.y) : "l"(a)); return r;
}
__device__ __forceinline__ u64 f2fma(u64 a, u64 b, u64 c) {
    u64 d; asm("fma.rn.f32x2 %0,%1,%2,%3;" : "=l"(d) : "l"(a), "l"(b), "l"(c)); return d;
}
// pack (lo,hi) floats -> bf16x2 (lo in low 16 bits)
__device__ __forceinline__ u32 pkbf(float lo, float hi) {
    u32 r; asm("cvt.rn.bf16x2.f32 %0,%1,%2;" : "=r"(r) : "f"(hi), "f"(lo)); return r;
}
__device__ __forceinline__ float bflo(u32 a) { return __uint_as_float(a << 16); }
__device__ __forceinline__ float bfhi(u32 a) { return __uint_as_float(a & 0xffff0000u); }

__device__ __forceinline__ void mma_bf16(float* c, u32 a0, u32 a1, u32 a2, u32 a3, u32 b0, u32 b1) {
    asm("mma.sync.aligned.m16n8k16.row.col.f32.bf16.bf16.f32 "
        "{%0,%1,%2,%3},{%4,%5,%6,%7},{%8,%9},{%0,%1,%2,%3};"
        : "+f"(c[0]), "+f"(c[1]), "+f"(c[2]), "+f"(c[3])
        : "r"(a0), "r"(a1), "r"(a2), "r"(a3), "r"(b0), "r"(b1));
}

// ---------------- device scratch ----------------
__device__ float g_Wf[E * E3];
__device__ float g_bf[E3];
__device__ float g_owt[E * E];
__device__ float g_alpha[KQ * E];
// mma-fragment-order operand caches (bf16 hi/lo split)
// Q: [h][qt(8)][dt(2)][hl(2)][lane(32)][reg(4)][half(2)] u16
__device__ __align__(16) unsigned short g_Qf[H * 8 * 2 * 2 * 32 * 8];
// K: [h][kt8(4096)][dt(2)][lane(32)][hl(2)][reg(2)][half(2)] u16
__device__ __align__(16) unsigned short g_Kf[H * 4096 * 2 * 32 * 8];
// V: [h][kt16(2048)][dt(4)][lane(32)][hl(2)][reg(2)][half(2)] u16
__device__ __align__(16) unsigned short g_Vf[H * 2048 * 4 * 32 * 8];
__device__ float g_pm[MAXSPLIT * H * KQ];
__device__ float g_pl[MAXSPLIT * H * KQ];
__device__ float g_po[MAXSPLIT * H * KQ * HD];

// ---------------- one-time weight fusion ----------------
__global__ void fuse_weights(const float* __restrict__ qkvw, const float* __restrict__ qkvb,
                             const float* __restrict__ inw,  const float* __restrict__ inb)
{
    __shared__ float wrow[E];
    int o = blockIdx.x, p = o / E, tid = threadIdx.x;
    wrow[tid] = inw[o * E + tid];
    __syncthreads();
    const float scale = 0.17677669529663687f;
    float acc = 0.f;
    int e = tid;
    #pragma unroll 4
    for (int j = 0; j < E; ++j) acc += wrow[j] * qkvw[(p * E + j) * E + e];
    if (p == 0) acc *= scale;
    g_Wf[e * E3 + o] = acc;
    if (tid < 32) {
        float s = 0.f;
        for (int j = tid; j < E; j += 32) s += wrow[j] * qkvb[p * E + j];
        #pragma unroll
        for (int off = 16; off; off >>= 1) s += __shfl_xor_sync(0xffffffffu, s, off);
        if (tid == 0) { float b = s + inb[o]; if (p == 0) b *= scale; g_bf[o] = b; }
    }
}

__global__ void transpose_ow(const float* __restrict__ outw)
{
    int j = blockIdx.x, i = threadIdx.x;
    g_owt[j * E + i] = outw[i * E + j];
}

// ---------------- initial LayerNorm ----------------
__global__ void init_ln(const float* __restrict__ mu0, const float* __restrict__ lng,
                        const float* __restrict__ lnb, float* __restrict__ out)
{
    __shared__ float red[10];
    __shared__ float mean_s, rstd_s;
    int k = blockIdx.x, tid = threadIdx.x;
    float x = mu0[k * E + tid];
    float s = x;
    #pragma unroll
    for (int off = 16; off; off >>= 1) s += __shfl_xor_sync(0xffffffffu, s, off);
    if ((tid & 31) == 0) red[tid >> 5] = s;
    __syncthreads();
    if (tid == 0) { float m = 0; for (int i = 0; i < 10; ++i) m += red[i]; mean_s = m / E; }
    __syncthreads();
    float d = x - mean_s;
    float v = d * d;
    #pragma unroll
    for (int off = 16; off; off >>= 1) v += __shfl_xor_sync(0xffffffffu, v, off);
    if ((tid & 31) == 0) red[tid >> 5] = v;
    __syncthreads();
    if (tid == 0) { float m = 0; for (int i = 0; i < 10; ++i) m += red[i]; rstd_s = rsqrtf(m / E + EPS); }
    __syncthreads();
    float y = d * rstd_s * lng[tid] + lnb[tid];
    g_alpha[k * E + tid] = y;
    out[k * E + tid] = y;
}

// store helper: split fp32 into bf16 hi/lo
__device__ __forceinline__ void bfsplit(float v, unsigned short& hi, unsigned short& lo) {
    __nv_bfloat16 bh = __float2bfloat16_rn(v);
    float r = v - __bfloat162float(bh);
    __nv_bfloat16 bl = __float2bfloat16_rn(r);
    hi = *(unsigned short*)&bh;
    lo = *(unsigned short*)&bl;
}

// ---------------- per-step fused projection -> fragment caches ----------------
__global__ __launch_bounds__(240) void proj_kernel(int t)
{
    __shared__ u64 as2[E];
    int tid = threadIdx.x;
    int o = blockIdx.x * 240 + tid;
    int k0 = blockIdx.y * 2;
    for (int i = tid; i < E; i += 240)
        as2[i] = pk2(g_alpha[k0 * E + i], g_alpha[(k0 + 1) * E + i]);
    __syncthreads();
    u64 acc = 0ull;
    #pragma unroll 16
    for (int e = 0; e < E; ++e) {
        float w = g_Wf[e * E3 + o];
        acc = f2fma(as2[e], pk2(w, w), acc);
    }
    float2 ar = upk2(acc);
    float b = g_bf[o];
    float va[2] = {ar.x + b, ar.y + b};

    if (o < E) {
        int hh = o >> 5, d = o & 31;
        int dt = d >> 4, dd = d & 15;
        int reg = ((dd >> 3) << 1), half = dd & 1;
        #pragma unroll
        for (int r = 0; r < 2; ++r) {
            int q = k0 + r;
            int qt = q >> 4, qr = q & 15;
            int rg = reg | ((qr >> 3) & 1);
            int li = (qr & 7) * 4 + ((dd & 7) >> 1);
            unsigned short hi, lo; bfsplit(va[r], hi, lo);
            int base = ((((hh * 8 + qt) * 2 + dt) * 2 + 0) * 32 + li) * 8 + rg * 2 + half;
            g_Qf[base] = hi;
            g_Qf[base + 256] = lo;      // hl stride = 32*8
        }
    } else if (o < 2 * E) {
        int e = o - E, hh = e >> 5, d = e & 31;
        int dt = d >> 4, dd = d & 15;
        int reg = dd >> 3, half = dd & 1;
        #pragma unroll
        for (int r = 0; r < 2; ++r) {
            int key = t * KQ + k0 + r;
            int kt = key >> 3, kr = key & 7;
            int li = kr * 4 + ((dd & 7) >> 1);
            unsigned short hi, lo; bfsplit(va[r], hi, lo);
            int base = (((hh * 4096 + kt) * 2 + dt) * 32 + li) * 8;
            g_Kf[base + reg * 2 + half] = hi;
            g_Kf[base + 4 + reg * 2 + half] = lo;
        }
    } else {
        int e = o - 2 * E, hh = e >> 5, d = e & 31;
        int dt = d >> 3, dd = d & 7;
        #pragma unroll
        for (int r = 0; r < 2; ++r) {
            int key = t * KQ + k0 + r;
            int kt = key >> 4, kk = key & 15;
            int reg = kk >> 3, half = kk & 1;
            int li = dd * 4 + ((kk & 7) >> 1);
            unsigned short hi, lo; bfsplit(va[r], hi, lo);
            int base = (((hh * 2048 + kt) * 4 + dt) * 32 + li) * 8;
            g_Vf[base + reg * 2 + half] = hi;
            g_Vf[base + 4 + reg * 2 + half] = lo;
        }
    }
}

// ---------------- attention: tensor-core flash kernel ----------------
// grid (H, split) x 256 threads (8 warps), warp w owns q rows w*16..w*16+15.
// No shared memory, no syncthreads; operands pre-laid-out in fragment order.
__global__ __launch_bounds__(256, 2) void attn_kernel(int t, int nchunk, int split)
{
    int tid = threadIdx.x, w = tid >> 5, lane = tid & 31;
    int h = blockIdx.x, sp = blockIdx.y;
    const uint4* Qp = (const uint4*)g_Qf;
    const uint4* Kp = (const uint4*)g_Kf;
    const uint4* Vp = (const uint4*)g_Vf;

    // Q fragments: qh/ql per d-tile; uint4 = (a0,a1,a2,a3)
    int qb = ((h * 8 + w) * 2) * 2 * 32;
    uint4 qh0 = Qp[qb + 0 * 32 + lane];
    uint4 ql0 = Qp[qb + 1 * 32 + lane];
    uint4 qh1 = Qp[qb + 2 * 32 + lane];
    uint4 ql1 = Qp[qb + 3 * 32 + lane];

    float acc[4][4];
    #pragma unroll
    for (int i = 0; i < 4; ++i)
        #pragma unroll
        for (int j = 0; j < 4; ++j) acc[i][j] = 0.f;
    float m0 = -1e30f, m1 = -1e30f, l0 = 0.f, l1 = 0.f;

    int cA = (sp * nchunk) / split, cB = ((sp + 1) * nchunk) / split;

    for (int c = cA; c < cB; ++c) {
        // ---- scores: 16q x 64k, 3-way split-bf16 ----
        float s[8][4];
        #pragma unroll
        for (int i = 0; i < 8; ++i) { s[i][0] = s[i][1] = s[i][2] = s[i][3] = 0.f; }
        int kb = (h * 4096 + c * 8) * 2 * 32;
        #pragma unroll
        for (int i = 0; i < 8; ++i) {
            uint4 kA = Kp[kb + (2 * i) * 32 + lane];       // dtile0: khi_b0,khi_b1,klo_b0,klo_b1
            uint4 kB = Kp[kb + (2 * i + 1) * 32 + lane];   // dtile1
            mma_bf16(s[i], qh0.x, qh0.y, qh0.z, qh0.w, kA.x, kA.y);
            mma_bf16(s[i], ql0.x, ql0.y, ql0.z, ql0.w, kA.x, kA.y);
            mma_bf16(s[i], qh0.x, qh0.y, qh0.z, qh0.w, kA.z, kA.w);
            mma_bf16(s[i], qh1.x, qh1.y, qh1.z, qh1.w, kB.x, kB.y);
            mma_bf16(s[i], ql1.x, ql1.y, ql1.z, ql1.w, kB.x, kB.y);
            mma_bf16(s[i], qh1.x, qh1.y, qh1.z, qh1.w, kB.z, kB.w);
        }

        // ---- online softmax (rows r0=lane/4, r1=r0+8) ----
        float mx0 = -1e30f, mx1 = -1e30f;
        #pragma unroll
        for (int i = 0; i < 8; ++i) {
            mx0 = fmaxf(mx0, fmaxf(s[i][0], s[i][1]));
            mx1 = fmaxf(mx1, fmaxf(s[i][2], s[i][3]));
        }
        mx0 = fmaxf(mx0, __shfl_xor_sync(0xffffffffu, mx0, 1));
        mx0 = fmaxf(mx0, __shfl_xor_sync(0xffffffffu, mx0, 2));
        mx1 = fmaxf(mx1, __shfl_xor_sync(0xffffffffu, mx1, 1));
        mx1 = fmaxf(mx1, __shfl_xor_sync(0xffffffffu, mx1, 2));
        float mn0 = fmaxf(m0, mx0), mn1 = fmaxf(m1, mx1);
        float corr0 = __expf(m0 - mn0), corr1 = __expf(m1 - mn1);
        float sum0 = 0.f, sum1 = 0.f;
        #pragma unroll
        for (int i = 0; i < 8; ++i) {
            s[i][0] = __expf(s[i][0] - mn0);
            s[i][1] = __expf(s[i][1] - mn0);
            sum0 += s[i][0] + s[i][1];
            s[i][2] = __expf(s[i][2] - mn1);
            s[i][3] = __expf(s[i][3] - mn1);
            sum1 += s[i][2] + s[i][3];
        }
        sum0 += __shfl_xor_sync(0xffffffffu, sum0, 1);
        sum0 += __shfl_xor_sync(0xffffffffu, sum0, 2);
        sum1 += __shfl_xor_sync(0xffffffffu, sum1, 1);
        sum1 += __shfl_xor_sync(0xffffffffu, sum1, 2);
        l0 = l0 * corr0 + sum0;
        l1 = l1 * corr1 + sum1;
        m0 = mn0; m1 = mn1;
        #pragma unroll
        for (int dt = 0; dt < 4; ++dt) {
            acc[dt][0] *= corr0; acc[dt][1] *= corr0;
            acc[dt][2] *= corr1; acc[dt][3] *= corr1;
        }

        // ---- AV: P (C-frag -> A-frag, split bf16), V from frag cache ----
        #pragma unroll
        for (int kt = 0; kt < 4; ++kt) {
            u32 pa0 = pkbf(s[2 * kt][0],     s[2 * kt][1]);
            u32 pa1 = pkbf(s[2 * kt][2],     s[2 * kt][3]);
            u32 pa2 = pkbf(s[2 * kt + 1][0], s[2 * kt + 1][1]);
            u32 pa3 = pkbf(s[2 * kt + 1][2], s[2 * kt + 1][3]);
            u32 pb0 = pkbf(s[2 * kt][0] - bflo(pa0),     s[2 * kt][1] - bfhi(pa0));
            u32 pb1 = pkbf(s[2 * kt][2] - bflo(pa1),     s[2 * kt][3] - bfhi(pa1));
            u32 pb2 = pkbf(s[2 * kt + 1][0] - bflo(pa2), s[2 * kt + 1][1] - bfhi(pa2));
            u32 pb3 = pkbf(s[2 * kt + 1][2] - bflo(pa3), s[2 * kt + 1][3] - bfhi(pa3));
            int vb = (h * 2048 + c * 4 + kt) * 4 * 32;
            #pragma unroll
            for (int dt = 0; dt < 4; ++dt) {
                uint4 v = Vp[vb + dt * 32 + lane];
                mma_bf16(acc[dt], pa0, pa1, pa2, pa3, v.x, v.y);
                mma_bf16(acc[dt], pb0, pb1, pb2, pb3, v.x, v.y);
                mma_bf16(acc[dt], pa0, pa1, pa2, pa3, v.z, v.w);
            }
        }
    }

    // ---- store partials ----
    int pbase = (sp * H + h) * KQ + w * 16;
    int r0 = lane >> 2, col0 = 2 * (lane & 3);
    #pragma unroll
    for (int dt = 0; dt < 4; ++dt) {
        *(float2*)&g_po[(pbase + r0) * HD + dt * 8 + col0]     = make_float2(acc[dt][0], acc[dt][1]);
        *(float2*)&g_po[(pbase + r0 + 8) * HD + dt * 8 + col0] = make_float2(acc[dt][2], acc[dt][3]);
    }
    if ((lane & 3) == 0) {
        g_pm[pbase + r0] = m0;     g_pl[pbase + r0] = l0;
        g_pm[pbase + r0 + 8] = m1; g_pl[pbase + r0 + 8] = l1;
    }
}

// ---------------- epilogue ----------------
__global__ __launch_bounds__(320) void epilogue_kernel(int t, int split, const float* __restrict__ outb,
                                const float* __restrict__ lng, const float* __restrict__ lnb,
                                float* __restrict__ out)
{
    __shared__ float o_sh[2][E];
    __shared__ float res[2][E];
    __shared__ float ws[2][H][MAXSPLIT];
    __shared__ float lcinv[2][H];
    __shared__ float mean2[2], rstd2[2];
    int tid = threadIdx.x;
    int k0 = blockIdx.x * 2;

    if (tid < 2 * H) {
        int r = tid / H, hh = tid % H;
        int row = k0 + r;
        float M = -1e30f;
        for (int sp = 0; sp < split; ++sp)
            M = fmaxf(M, g_pm[(sp * H + hh) * KQ + row]);
        float lsum = 0.f;
        for (int sp = 0; sp < split; ++sp) {
            float wv = __expf(g_pm[(sp * H + hh) * KQ + row] - M);
            ws[r][hh][sp] = wv;
            lsum += wv * g_pl[(sp * H + hh) * KQ + row];
        }
        lcinv[r][hh] = 1.f / lsum;
    }
    __syncthreads();

    for (int idx = tid; idx < 2 * E; idx += 320) {
        int r = idx / E, e = idx - r * E;
        int hh = e >> 5, d = e & 31, row = k0 + r;
        float o = 0.f;
        for (int sp = 0; sp < split; ++sp)
            o += ws[r][hh][sp] * g_po[((sp * H + hh) * KQ + row) * HD + d];
        o_sh[r][e] = o * lcinv[r][hh];
    }
    __syncthreads();

    u64 acc = 0ull;
    int i = tid;
    #pragma unroll 4
    for (int j = 0; j < E; ++j) {
        float wv = g_owt[j * E + i];
        acc = f2fma(pk2(o_sh[0][j], o_sh[1][j]), pk2(wv, wv), acc);
    }
    float2 av = upk2(acc);
    float ob = outb[i];
    res[0][i] = av.x + ob + g_alpha[(k0 + 0) * E + i];
    res[1][i] = av.y + ob + g_alpha[(k0 + 1) * E + i];
    __syncthreads();

    int w = tid >> 5, lane = tid & 31;
    if (w < 2) {
        float s = 0.f;
        for (int ii = lane; ii < E; ii += 32) s += res[w][ii];
        #pragma unroll
        for (int off = 16; off; off >>= 1) s += __shfl_xor_sync(0xffffffffu, s, off);
        float mean = s / E;
        float v = 0.f;
        for (int ii = lane; ii < E; ii += 32) { float d2 = res[w][ii] - mean; v += d2 * d2; }
        #pragma unroll
        for (int off = 16; off; off >>= 1) v += __shfl_xor_sync(0xffffffffu, v, off);
        if (lane == 0) { mean2[w] = mean; rstd2[w] = rsqrtf(v / E + EPS); }
    }
    __syncthreads();
    float gg = lng[tid], bb = lnb[tid];
    #pragma unroll
    for (int r = 0; r < 2; ++r) {
        float y = (res[r][tid] - mean2[r]) * rstd2[r] * gg + bb;
        g_alpha[(k0 + r) * E + tid] = y;
        out[((size_t)(t + 1) * KQ + k0 + r) * E + tid] = y;
    }
}

// ---------------- host ----------------
extern "C" void kernel_launch(void* const* d_in, const int* in_sizes, int n_in,
                              void* d_out, int out_size)
{
    const float* mu0   = (const float*)d_in[0];
    const float* qkvw  = (const float*)d_in[1];
    const float* qkvb  = (const float*)d_in[2];
    const float* inw   = (const float*)d_in[3];
    const float* inb   = (const float*)d_in[4];
    const float* outw  = (const float*)d_in[5];
    const float* outb  = (const float*)d_in[6];
    const float* lng   = (const float*)d_in[7];
    const float* lnb   = (const float*)d_in[8];
    float* out = (float*)d_out;

    fuse_weights<<<E3, E>>>(qkvw, qkvb, inw, inb);
    transpose_ow<<<E, E>>>(outw);
    init_ln<<<KQ, E>>>(mu0, lng, lnb, out);

    for (int t = 0; t < TM1; ++t) {
        proj_kernel<<<dim3(4, 64), 240>>>(t);
        int nchunk = 2 * (t + 1);
        int split = (nchunk < MAXSPLIT) ? nchunk : MAXSPLIT;
        attn_kernel<<<dim3(H, split), 256>>>(t, nchunk, split);
        epilogue_kernel<<<64, 320>>>(t, split, outb, lng, lnb, out);
    }
}